// round 10
// baseline (speedup 1.0000x reference)
#include <cuda_runtime.h>
#include <cuda_bf16.h>

#define N_NODES 50000
#define IN_CH   64
#define REL_DIM 32
#define N_EDGES 800000
#define NEG_SLOPE 0.01f

#define NBLK   592
#define NTHR   256
#define GT     (NBLK * NTHR)
#define GWARPS (NBLK * 8)
#define NCHUNK ((N_NODES + 255) / 256)   // 196
#define NBAR   13

// ---------------- scratch ----------------
__device__ float    g_rp   [(size_t)N_EDGES * REL_DIM];  // r permuted to dst-CSR order
__device__ float    g_ew1  [N_EDGES];                    // permuted
__device__ float    g_ew2  [N_EDGES];                    // permuted
__device__ float    g_alpha[N_EDGES];                    // permuted
__device__ float    g_x    [N_NODES * IN_CH];
__device__ float    g_h    [N_NODES * IN_CH];
__device__ float    g_ai   [N_NODES];
__device__ float    g_aj   [N_NODES];
__device__ unsigned g_mkey1[N_NODES];
__device__ float    g_ssum1[N_NODES];
__device__ unsigned g_mkey2[N_NODES];
__device__ float    g_ssum2[N_NODES];
__device__ int      g_deg  [N_NODES];
__device__ int      g_rowst[N_NODES];
__device__ int      g_curs [N_NODES];
__device__ int      g_bsum [NCHUNK];
__device__ int      g_boff [NCHUNK];
__device__ int2     g_edge [N_EDGES];                    // {src, dst} permuted
__device__ float    g_v1   [REL_DIM];
__device__ float    g_v2   [REL_DIM];
__device__ float    g_ewc  [2];
__device__ unsigned gA[NBAR];
__device__ unsigned gD[NBAR];

struct SmemXF { float Wt[IN_CH * IN_CH]; float bsh[IN_CH], ais[IN_CH], ajs[IN_CH]; };
struct SmemGT { float Ws[REL_DIM * IN_CH]; float Bs[IN_CH]; };
struct SmemEW { float sv1[REL_DIM], sv2[REL_DIM], sc[2]; };
struct SmemSC { int wsum[8]; };
union Smem { SmemXF xf; SmemGT gt; SmemEW ew; SmemSC sc; };

__device__ __forceinline__ unsigned fkey(float f) {
    unsigned b = __float_as_uint(f);
    return (b & 0x80000000u) ? ~b : (b | 0x80000000u);
}
__device__ __forceinline__ float funkey(unsigned u) {
    unsigned b = (u & 0x80000000u) ? (u & 0x7fffffffu) : ~u;
    return __uint_as_float(b);
}

// ---- software grid barrier (arrive/depart, self-resetting for replay) ----------
__device__ __forceinline__ void gsync(int id) {
    __syncthreads();
    if (threadIdx.x == 0) {
        __threadfence();
        atomicAdd(&gA[id], 1u);
        while (*((volatile unsigned*)&gA[id]) < (unsigned)NBLK) __nanosleep(64);
        unsigned d = atomicAdd(&gD[id], 1u);
        if (d == (unsigned)(NBLK - 1)) {
            *((volatile unsigned*)&gA[id]) = 0u;
            *((volatile unsigned*)&gD[id]) = 0u;
        }
        __threadfence();
    }
    __syncthreads();
}

// ---- node transform + attention scalars (warp per node, grid-strided) ----------
__device__ void do_transform(Smem* sm, const float* __restrict__ in,
                             const float* __restrict__ W, const float* __restrict__ b,
                             const float* __restrict__ aiw, const float* __restrict__ aib,
                             const float* __restrict__ ajw, const float* __restrict__ ajb,
                             int gwarp, int lane)
{
    int tid = threadIdx.x;
    for (int i = tid; i < IN_CH * IN_CH; i += NTHR) {
        int c = i >> 6, k = i & 63;
        sm->xf.Wt[k * IN_CH + c] = W[i];
    }
    if (tid < IN_CH) { sm->xf.bsh[tid] = b[tid]; sm->xf.ais[tid] = aiw[tid]; sm->xf.ajs[tid] = ajw[tid]; }
    float aib0 = aib[0], ajb0 = ajb[0];
    __syncthreads();

    for (int n = gwarp; n < N_NODES; n += GWARPS) {
        float iv0 = in[(size_t)n * IN_CH + lane];
        float iv1 = in[(size_t)n * IN_CH + 32 + lane];
        float acc0 = sm->xf.bsh[lane], acc1 = sm->xf.bsh[32 + lane];
#pragma unroll
        for (int k = 0; k < 32; k++) {
            float v = __shfl_sync(0xffffffffu, iv0, k);
            acc0 += v * sm->xf.Wt[k * IN_CH + lane];
            acc1 += v * sm->xf.Wt[k * IN_CH + 32 + lane];
        }
#pragma unroll
        for (int k = 0; k < 32; k++) {
            float v = __shfl_sync(0xffffffffu, iv1, k);
            acc0 += v * sm->xf.Wt[(k + 32) * IN_CH + lane];
            acc1 += v * sm->xf.Wt[(k + 32) * IN_CH + 32 + lane];
        }
        g_x[(size_t)n * IN_CH + lane]      = acc0;
        g_x[(size_t)n * IN_CH + 32 + lane] = acc1;

        float ap = acc0 * sm->xf.ais[lane] + acc1 * sm->xf.ais[32 + lane];
        float jp = acc0 * sm->xf.ajs[lane] + acc1 * sm->xf.ajs[32 + lane];
#pragma unroll
        for (int o = 16; o > 0; o >>= 1) {
            ap += __shfl_xor_sync(0xffffffffu, ap, o);
            jp += __shfl_xor_sync(0xffffffffu, jp, o);
        }
        if (lane == 0) { g_ai[n] = ap + aib0; g_aj[n] = jp + ajb0; }
    }
    __syncthreads();
}

// ---- alpha + segment max over src (permuted order) ------------------------------
__device__ void do_alpha_max(const float* __restrict__ ew, unsigned* __restrict__ mkey, int gtid)
{
    for (int p = gtid; p < N_EDGES; p += GT) {
        int2 sd = g_edge[p];
        float a = g_ai[sd.y] + g_aj[sd.x] + ew[p];
        a = a > 0.0f ? a : NEG_SLOPE * a;
        g_alpha[p] = a;
        atomicMax(&mkey[sd.x], fkey(a));
    }
}

// ---- ex = exp(alpha - m[src]); segment sum over src (permuted) ------------------
__device__ void do_exp_sum(const unsigned* __restrict__ mkey, float* __restrict__ ssum, int gtid)
{
    for (int p = gtid; p < N_EDGES; p += GT) {
        int s = g_edge[p].x;
        float m = funkey(mkey[s]);
        float ex = __expf(g_alpha[p] - m);
        g_alpha[p] = ex;
        atomicAdd(&ssum[s], ex);
    }
}

// ---- gather-aggregate per dst node (warp per node, streaming r) -----------------
__device__ void do_gather(Smem* sm,
                          const float* __restrict__ relW, const float* __restrict__ relB,
                          const float* __restrict__ ssum, float* __restrict__ out,
                          int gwarp, int lane)
{
    int tid = threadIdx.x;
    for (int i = tid; i < REL_DIM * IN_CH; i += NTHR) {
        int c = i >> 5, k = i & 31;
        sm->gt.Ws[k * IN_CH + c] = relW[i];
    }
    if (tid < IN_CH) sm->gt.Bs[tid] = relB[tid];
    __syncthreads();
    const float2* Ws2 = reinterpret_cast<const float2*>(sm->gt.Ws);
    const float2* Bs2 = reinterpret_cast<const float2*>(sm->gt.Bs);

    for (int node = gwarp; node < N_NODES; node += GWARPS) {
        int start = g_rowst[node];
        int deg   = g_deg[node];

        float2 acc = make_float2(0.f, 0.f);
        float accr = 0.f, csum = 0.f;

        int base = 0;
        for (; base + 32 <= deg; base += 32) {
            int pp = start + base + lane;
            int sj_own = g_edge[pp].x;
            float cf = __fdividef(g_alpha[pp], ssum[sj_own] + 1e-16f);
            csum += cf;
#pragma unroll 8
            for (int j = 0; j < 32; j++) {
                float cj = __shfl_sync(0xffffffffu, cf, j);
                int   sj = __shfl_sync(0xffffffffu, sj_own, j);
                float2 xv = *reinterpret_cast<const float2*>(g_x + (size_t)sj * IN_CH + 2 * lane);
                acc.x += cj * xv.x;
                acc.y += cj * xv.y;
                accr  += cj * g_rp[(size_t)(start + base + j) * REL_DIM + lane];
            }
        }
        int m = deg - base;
        if (m > 0) {
            int sj_own = 0;
            float cf = 0.f;
            if (lane < m) {
                int pp = start + base + lane;
                sj_own = g_edge[pp].x;
                cf = __fdividef(g_alpha[pp], ssum[sj_own] + 1e-16f);
            }
            csum += cf;
#pragma unroll 8
            for (int j = 0; j < 32; j++) {
                if (j < m) {
                    float cj = __shfl_sync(0xffffffffu, cf, j);
                    int   sj = __shfl_sync(0xffffffffu, sj_own, j);
                    float2 xv = *reinterpret_cast<const float2*>(g_x + (size_t)sj * IN_CH + 2 * lane);
                    acc.x += cj * xv.x;
                    acc.y += cj * xv.y;
                    accr  += cj * g_rp[(size_t)(start + base + j) * REL_DIM + lane];
                }
            }
        }

#pragma unroll
        for (int o = 16; o > 0; o >>= 1)
            csum += __shfl_xor_sync(0xffffffffu, csum, o);

        float2 oo = make_float2(0.f, 0.f);
#pragma unroll
        for (int k = 0; k < REL_DIM; k++) {
            float v = __shfl_sync(0xffffffffu, accr, k);
            float2 w = Ws2[k * 32 + lane];
            oo.x += v * w.x;
            oo.y += v * w.y;
        }

        float2 bb = Bs2[lane];
        float r0 = acc.x + oo.x + csum * bb.x;
        float r1 = acc.y + oo.y + csum * bb.y;
        *reinterpret_cast<float2*>(out + (size_t)node * IN_CH + 2 * lane) =
            make_float2(fmaxf(r0, 0.f), fmaxf(r1, 0.f));
    }
    __syncthreads();
}

// =================================================================================
__global__ void __launch_bounds__(NTHR, 4)
k_main(const float* __restrict__ feat, const int* __restrict__ src, const int* __restrict__ dst,
       const float* __restrict__ r, const float* __restrict__ relW, const float* __restrict__ relB,
       const float* c1_lw, const float* c1_lb, const float* c1_aiw, const float* c1_aib,
       const float* c1_ajw, const float* c1_ajb, const float* c1_eww, const float* c1_ewb,
       const float* c2_lw, const float* c2_lb, const float* c2_aiw, const float* c2_aib,
       const float* c2_ajw, const float* c2_ajb, const float* c2_eww, const float* c2_ewb,
       float* __restrict__ out)
{
    __shared__ Smem sm;
    int tid  = threadIdx.x;
    int blk  = blockIdx.x;
    int gtid = blk * NTHR + tid;
    int lane = tid & 31;
    int gwarp = blk * 8 + (tid >> 5);

    // ---------------- P0: init + ewvec ----------------
    for (int i = gtid; i < N_NODES; i += GT) {
        g_deg[i] = 0;
        g_mkey1[i] = 0u; g_ssum1[i] = 0.0f;
        g_mkey2[i] = 0u; g_ssum2[i] = 0.0f;
    }
    if (blk == 0) {
        int t = tid;
        if (t < REL_DIM) {
            float a1 = 0.f, a2 = 0.f;
#pragma unroll
            for (int c = 0; c < IN_CH; c++) {
                float w = relW[c * REL_DIM + t];
                a1 += w * c1_eww[c];
                a2 += w * c2_eww[c];
            }
            g_v1[t] = a1; g_v2[t] = a2;
        } else if (t == 32) {
            float s = 0.f;
            for (int c = 0; c < IN_CH; c++) s += relB[c] * c1_eww[c];
            g_ewc[0] = s + c1_ewb[0];
        } else if (t == 33) {
            float s = 0.f;
            for (int c = 0; c < IN_CH; c++) s += relB[c] * c2_eww[c];
            g_ewc[1] = s + c2_ewb[0];
        }
    }
    gsync(0);

    // ---------------- P1: dst histogram + transform L1 ----------------
    for (int e = gtid; e < N_EDGES; e += GT)
        atomicAdd(&g_deg[dst[e]], 1);
    do_transform(&sm, feat, c1_lw, c1_lb, c1_aiw, c1_aib, c1_ajw, c1_ajb, gwarp, lane);
    gsync(1);

    // ---------------- P2: scan1 (block-local) ----------------
    if (blk < NCHUNK) {
        int i = blk * 256 + tid;
        int v = (i < N_NODES) ? g_deg[i] : 0;
        int x = v;
#pragma unroll
        for (int off = 1; off < 32; off <<= 1) {
            int y = __shfl_up_sync(0xffffffffu, x, off);
            if (lane >= off) x += y;
        }
        int wid = tid >> 5;
        if (lane == 31) sm.sc.wsum[wid] = x;
        __syncthreads();
        if (wid == 0) {
            int s = (lane < 8) ? sm.sc.wsum[lane] : 0;
#pragma unroll
            for (int off = 1; off < 8; off <<= 1) {
                int y = __shfl_up_sync(0xffffffffu, s, off);
                if (lane >= off) s += y;
            }
            if (lane < 8) sm.sc.wsum[lane] = s;
        }
        __syncthreads();
        int woff = (wid == 0) ? 0 : sm.sc.wsum[wid - 1];
        if (i < N_NODES) g_rowst[i] = woff + x - v;
        if (tid == 255) g_bsum[blk] = woff + x;
        __syncthreads();
    }
    gsync(2);

    // ---------------- P3: scan2 (block 0) ----------------
    if (blk == 0) {
        int t = tid, wid = t >> 5;
        int v = (t < NCHUNK) ? g_bsum[t] : 0;
        int x = v;
#pragma unroll
        for (int off = 1; off < 32; off <<= 1) {
            int y = __shfl_up_sync(0xffffffffu, x, off);
            if (lane >= off) x += y;
        }
        if (lane == 31) sm.sc.wsum[wid] = x;
        __syncthreads();
        if (wid == 0) {
            int s = (lane < 8) ? sm.sc.wsum[lane] : 0;
#pragma unroll
            for (int off = 1; off < 8; off <<= 1) {
                int y = __shfl_up_sync(0xffffffffu, s, off);
                if (lane >= off) s += y;
            }
            if (lane < 8) sm.sc.wsum[lane] = s;
        }
        __syncthreads();
        int woff = (wid == 0) ? 0 : sm.sc.wsum[wid - 1];
        if (t < NCHUNK) g_boff[t] = woff + x - v;
        __syncthreads();
    }
    gsync(3);

    // ---------------- P4: scan3 ----------------
    for (int i = gtid; i < N_NODES; i += GT) {
        int v = g_rowst[i] + g_boff[i >> 8];
        g_rowst[i] = v;
        g_curs[i]  = v;
    }
    gsync(4);

    // ---------------- P5: scatter + ew + r-permute (one streaming pass over r) ---
    if (tid < REL_DIM) { sm.ew.sv1[tid] = g_v1[tid]; sm.ew.sv2[tid] = g_v2[tid]; }
    if (tid < 2) sm.ew.sc[tid] = g_ewc[tid];
    __syncthreads();
    {
        float c0 = sm.ew.sc[0], c1 = sm.ew.sc[1];
        for (int e = gtid; e < N_EDGES; e += GT) {
            int d = dst[e], s = src[e];
            int p = atomicAdd(&g_curs[d], 1);
            const float4* rp = reinterpret_cast<const float4*>(r + (size_t)e * REL_DIM);
            float4* wp = reinterpret_cast<float4*>(g_rp + (size_t)p * REL_DIM);
            float a1 = 0.f, a2 = 0.f;
#pragma unroll
            for (int q = 0; q < 8; q++) {
                float4 f = rp[q];
                a1 += f.x * sm.ew.sv1[4*q] + f.y * sm.ew.sv1[4*q+1] + f.z * sm.ew.sv1[4*q+2] + f.w * sm.ew.sv1[4*q+3];
                a2 += f.x * sm.ew.sv2[4*q] + f.y * sm.ew.sv2[4*q+1] + f.z * sm.ew.sv2[4*q+2] + f.w * sm.ew.sv2[4*q+3];
                wp[q] = f;
            }
            g_ew1[p] = a1 + c0;
            g_ew2[p] = a2 + c1;
            g_edge[p] = make_int2(s, d);
        }
    }
    __syncthreads();
    gsync(5);

    // ---------------- P6: alpha_max L1 ----------------
    do_alpha_max(g_ew1, g_mkey1, gtid);
    gsync(6);

    // ---------------- P7: exp_sum L1 ----------------
    do_exp_sum(g_mkey1, g_ssum1, gtid);
    gsync(7);

    // ---------------- P8: gather L1 -> g_h ----------------
    do_gather(&sm, relW, relB, g_ssum1, g_h, gwarp, lane);
    gsync(8);

    // ---------------- P9: transform L2 ----------------
    do_transform(&sm, g_h, c2_lw, c2_lb, c2_aiw, c2_aib, c2_ajw, c2_ajb, gwarp, lane);
    gsync(9);

    // ---------------- P10: alpha_max L2 ----------------
    do_alpha_max(g_ew2, g_mkey2, gtid);
    gsync(10);

    // ---------------- P11: exp_sum L2 ----------------
    do_exp_sum(g_mkey2, g_ssum2, gtid);
    gsync(11);

    // ---------------- P12: gather L2 -> out ----------------
    do_gather(&sm, relW, relB, g_ssum2, out, gwarp, lane);
}

extern "C" void kernel_launch(void* const* d_in, const int* in_sizes, int n_in,
                              void* d_out, int out_size)
{
    const float* feat   = (const float*)d_in[0];
    const int*   eidx   = (const int*)  d_in[1];
    const float* r      = (const float*)d_in[2];
    const float* rel_w  = (const float*)d_in[3];
    const float* rel_b  = (const float*)d_in[4];
    const float* c1_lw  = (const float*)d_in[5];
    const float* c1_lb  = (const float*)d_in[6];
    const float* c1_aiw = (const float*)d_in[7];
    const float* c1_aib = (const float*)d_in[8];
    const float* c1_ajw = (const float*)d_in[9];
    const float* c1_ajb = (const float*)d_in[10];
    const float* c1_eww = (const float*)d_in[11];
    const float* c1_ewb = (const float*)d_in[12];
    const float* c2_lw  = (const float*)d_in[13];
    const float* c2_lb  = (const float*)d_in[14];
    const float* c2_aiw = (const float*)d_in[15];
    const float* c2_aib = (const float*)d_in[16];
    const float* c2_ajw = (const float*)d_in[17];
    const float* c2_ajb = (const float*)d_in[18];
    const float* c2_eww = (const float*)d_in[19];
    const float* c2_ewb = (const float*)d_in[20];
    float* out = (float*)d_out;

    const int* src = eidx;
    const int* dst = eidx + N_EDGES;

    k_main<<<NBLK, NTHR>>>(feat, src, dst, r, rel_w, rel_b,
                           c1_lw, c1_lb, c1_aiw, c1_aib, c1_ajw, c1_ajb, c1_eww, c1_ewb,
                           c2_lw, c2_lb, c2_aiw, c2_aib, c2_ajw, c2_ajb, c2_eww, c2_ewb,
                           out);
}

// round 11
// speedup vs baseline: 1.2366x; 1.2366x over previous
#include <cuda_runtime.h>
#include <cuda_bf16.h>

#define N_NODES 50000
#define IN_CH   64
#define REL_DIM 32
#define N_EDGES 800000
#define NEG_SLOPE 0.01f

#define NBLK   888            // 6 blocks/SM x 148 SMs — all co-resident
#define NTHR   256
#define GT     (NBLK * NTHR)
#define GWARPS (NBLK * 8)
#define NCHUNK ((N_NODES + 255) / 256)   // 196
#define NBAR   12

// ---------------- scratch ----------------
__device__ float    g_ew1  [N_EDGES];
__device__ float    g_ew2  [N_EDGES];
__device__ float    g_alpha[N_EDGES];
__device__ float    g_x    [N_NODES * IN_CH];
__device__ float    g_h    [N_NODES * IN_CH];
__device__ float    g_ai   [N_NODES];
__device__ float    g_aj   [N_NODES];
__device__ unsigned g_mkey1[N_NODES];
__device__ float    g_ssum1[N_NODES];
__device__ unsigned g_mkey2[N_NODES];
__device__ float    g_ssum2[N_NODES];
__device__ int      g_deg  [N_NODES];
__device__ int      g_rowst[N_NODES];
__device__ int      g_curs [N_NODES];
__device__ int      g_bsum [NCHUNK];
__device__ int      g_boff [NCHUNK];
__device__ int2     g_edge [N_EDGES];          // {src, eid} in dst-CSR order
__device__ float    g_v1   [REL_DIM];
__device__ float    g_v2   [REL_DIM];
__device__ float    g_ewc  [2];
__device__ unsigned gA[NBAR];
__device__ unsigned gD[NBAR];

struct SmemXF { float Wt[IN_CH * IN_CH]; float bsh[IN_CH], ais[IN_CH], ajs[IN_CH]; };
struct SmemGT { float Ws[REL_DIM * IN_CH]; float Bs[IN_CH]; };
struct SmemEW { float sv1[REL_DIM], sv2[REL_DIM], sc[2]; };
struct SmemSC { int wsum[8]; };
union Smem { SmemXF xf; SmemGT gt; SmemEW ew; SmemSC sc; };

__device__ __forceinline__ unsigned fkey(float f) {
    unsigned b = __float_as_uint(f);
    return (b & 0x80000000u) ? ~b : (b | 0x80000000u);
}
__device__ __forceinline__ float funkey(unsigned u) {
    unsigned b = (u & 0x80000000u) ? (u & 0x7fffffffu) : ~u;
    return __uint_as_float(b);
}

// ---- software grid barrier (arrive/depart, self-resetting for replay) ----------
__device__ __forceinline__ void gsync(int id) {
    __syncthreads();
    if (threadIdx.x == 0) {
        __threadfence();
        atomicAdd(&gA[id], 1u);
        while (*((volatile unsigned*)&gA[id]) < (unsigned)NBLK) __nanosleep(64);
        unsigned d = atomicAdd(&gD[id], 1u);
        if (d == (unsigned)(NBLK - 1)) {
            *((volatile unsigned*)&gA[id]) = 0u;
            *((volatile unsigned*)&gD[id]) = 0u;
        }
        __threadfence();
    }
    __syncthreads();
}

// ---- node transform + attention scalars (warp per node, grid-strided) ----------
__device__ void do_transform(Smem* sm, const float* __restrict__ in,
                             const float* __restrict__ W, const float* __restrict__ b,
                             const float* __restrict__ aiw, const float* __restrict__ aib,
                             const float* __restrict__ ajw, const float* __restrict__ ajb,
                             int gwarp, int lane)
{
    int tid = threadIdx.x;
    for (int i = tid; i < IN_CH * IN_CH; i += NTHR) {
        int c = i >> 6, k = i & 63;
        sm->xf.Wt[k * IN_CH + c] = W[i];
    }
    if (tid < IN_CH) { sm->xf.bsh[tid] = b[tid]; sm->xf.ais[tid] = aiw[tid]; sm->xf.ajs[tid] = ajw[tid]; }
    float aib0 = aib[0], ajb0 = ajb[0];
    __syncthreads();

    for (int n = gwarp; n < N_NODES; n += GWARPS) {
        float iv0 = in[(size_t)n * IN_CH + lane];
        float iv1 = in[(size_t)n * IN_CH + 32 + lane];
        float acc0 = sm->xf.bsh[lane], acc1 = sm->xf.bsh[32 + lane];
#pragma unroll
        for (int k = 0; k < 32; k++) {
            float v = __shfl_sync(0xffffffffu, iv0, k);
            acc0 += v * sm->xf.Wt[k * IN_CH + lane];
            acc1 += v * sm->xf.Wt[k * IN_CH + 32 + lane];
        }
#pragma unroll
        for (int k = 0; k < 32; k++) {
            float v = __shfl_sync(0xffffffffu, iv1, k);
            acc0 += v * sm->xf.Wt[(k + 32) * IN_CH + lane];
            acc1 += v * sm->xf.Wt[(k + 32) * IN_CH + 32 + lane];
        }
        g_x[(size_t)n * IN_CH + lane]      = acc0;
        g_x[(size_t)n * IN_CH + 32 + lane] = acc1;

        float ap = acc0 * sm->xf.ais[lane] + acc1 * sm->xf.ais[32 + lane];
        float jp = acc0 * sm->xf.ajs[lane] + acc1 * sm->xf.ajs[32 + lane];
#pragma unroll
        for (int o = 16; o > 0; o >>= 1) {
            ap += __shfl_xor_sync(0xffffffffu, ap, o);
            jp += __shfl_xor_sync(0xffffffffu, jp, o);
        }
        if (lane == 0) { g_ai[n] = ap + aib0; g_aj[n] = jp + ajb0; }
    }
    __syncthreads();
}

// ---- alpha + segment max over src ----------------------------------------------
__device__ void do_alpha_max(const int* __restrict__ src, const int* __restrict__ dst,
                             const float* __restrict__ ew, unsigned* __restrict__ mkey, int gtid)
{
    for (int i = gtid; i < N_EDGES; i += GT) {
        int s = src[i], d = dst[i];
        float a = g_ai[d] + g_aj[s] + ew[i];
        a = a > 0.0f ? a : NEG_SLOPE * a;
        g_alpha[i] = a;
        atomicMax(&mkey[s], fkey(a));
    }
}

// ---- ex = exp(alpha - m[src]); segment sum over src ----------------------------
__device__ void do_exp_sum(const int* __restrict__ src,
                           const unsigned* __restrict__ mkey, float* __restrict__ ssum, int gtid)
{
    for (int i = gtid; i < N_EDGES; i += GT) {
        int s = src[i];
        float m = funkey(mkey[s]);
        float ex = __expf(g_alpha[i] - m);
        g_alpha[i] = ex;
        atomicAdd(&ssum[s], ex);
    }
}

// ---- gather-aggregate per dst node (warp per node, no atomics) ------------------
__device__ void do_gather(Smem* sm, const float* __restrict__ r,
                          const float* __restrict__ relW, const float* __restrict__ relB,
                          const float* __restrict__ ssum, float* __restrict__ out,
                          int gwarp, int lane)
{
    int tid = threadIdx.x;
    for (int i = tid; i < REL_DIM * IN_CH; i += NTHR) {
        int c = i >> 5, k = i & 31;
        sm->gt.Ws[k * IN_CH + c] = relW[i];
    }
    if (tid < IN_CH) sm->gt.Bs[tid] = relB[tid];
    __syncthreads();
    const float2* Ws2 = reinterpret_cast<const float2*>(sm->gt.Ws);
    const float2* Bs2 = reinterpret_cast<const float2*>(sm->gt.Bs);

    for (int node = gwarp; node < N_NODES; node += GWARPS) {
        int start = g_rowst[node];
        int deg   = g_deg[node];

        float2 acc = make_float2(0.f, 0.f);
        float accr = 0.f, csum = 0.f;

        int base = 0;
        for (; base + 32 <= deg; base += 32) {
            int2 se = g_edge[start + base + lane];
            float cf = __fdividef(g_alpha[se.y], ssum[se.x] + 1e-16f);
            csum += cf;
#pragma unroll 8
            for (int j = 0; j < 32; j++) {
                float cj = __shfl_sync(0xffffffffu, cf,   j);
                int   sj = __shfl_sync(0xffffffffu, se.x, j);
                int   ej = __shfl_sync(0xffffffffu, se.y, j);
                float2 xv = *reinterpret_cast<const float2*>(g_x + (size_t)sj * IN_CH + 2 * lane);
                acc.x += cj * xv.x;
                acc.y += cj * xv.y;
                accr  += cj * r[(size_t)ej * REL_DIM + lane];
            }
        }
        int m = deg - base;
        if (m > 0) {
            int2 se = make_int2(0, 0);
            float cf = 0.f;
            if (lane < m) {
                se = g_edge[start + base + lane];
                cf = __fdividef(g_alpha[se.y], ssum[se.x] + 1e-16f);
            }
            csum += cf;
#pragma unroll 8
            for (int j = 0; j < 32; j++) {
                if (j < m) {
                    float cj = __shfl_sync(0xffffffffu, cf,   j);
                    int   sj = __shfl_sync(0xffffffffu, se.x, j);
                    int   ej = __shfl_sync(0xffffffffu, se.y, j);
                    float2 xv = *reinterpret_cast<const float2*>(g_x + (size_t)sj * IN_CH + 2 * lane);
                    acc.x += cj * xv.x;
                    acc.y += cj * xv.y;
                    accr  += cj * r[(size_t)ej * REL_DIM + lane];
                }
            }
        }

#pragma unroll
        for (int o = 16; o > 0; o >>= 1)
            csum += __shfl_xor_sync(0xffffffffu, csum, o);

        float2 oo = make_float2(0.f, 0.f);
#pragma unroll
        for (int k = 0; k < REL_DIM; k++) {
            float v = __shfl_sync(0xffffffffu, accr, k);
            float2 w = Ws2[k * 32 + lane];
            oo.x += v * w.x;
            oo.y += v * w.y;
        }

        float2 bb = Bs2[lane];
        float r0 = acc.x + oo.x + csum * bb.x;
        float r1 = acc.y + oo.y + csum * bb.y;
        *reinterpret_cast<float2*>(out + (size_t)node * IN_CH + 2 * lane) =
            make_float2(fmaxf(r0, 0.f), fmaxf(r1, 0.f));
    }
    __syncthreads();
}

// =================================================================================
__global__ void __launch_bounds__(NTHR, 6)
k_main(const float* __restrict__ feat, const int* __restrict__ src, const int* __restrict__ dst,
       const float* __restrict__ r, const float* __restrict__ relW, const float* __restrict__ relB,
       const float* c1_lw, const float* c1_lb, const float* c1_aiw, const float* c1_aib,
       const float* c1_ajw, const float* c1_ajb, const float* c1_eww, const float* c1_ewb,
       const float* c2_lw, const float* c2_lb, const float* c2_aiw, const float* c2_aib,
       const float* c2_ajw, const float* c2_ajb, const float* c2_eww, const float* c2_ewb,
       float* __restrict__ out)
{
    __shared__ Smem sm;
    int tid  = threadIdx.x;
    int blk  = blockIdx.x;
    int gtid = blk * NTHR + tid;
    int lane = tid & 31;
    int gwarp = blk * 8 + (tid >> 5);

    // ---------------- P0: init + ewvec ----------------
    for (int i = gtid; i < N_NODES; i += GT) {
        g_deg[i] = 0;
        g_mkey1[i] = 0u; g_ssum1[i] = 0.0f;
        g_mkey2[i] = 0u; g_ssum2[i] = 0.0f;
    }
    if (blk == 0) {
        int t = tid;
        if (t < REL_DIM) {
            float a1 = 0.f, a2 = 0.f;
#pragma unroll
            for (int c = 0; c < IN_CH; c++) {
                float w = relW[c * REL_DIM + t];
                a1 += w * c1_eww[c];
                a2 += w * c2_eww[c];
            }
            g_v1[t] = a1; g_v2[t] = a2;
        } else if (t == 32) {
            float s = 0.f;
            for (int c = 0; c < IN_CH; c++) s += relB[c] * c1_eww[c];
            g_ewc[0] = s + c1_ewb[0];
        } else if (t == 33) {
            float s = 0.f;
            for (int c = 0; c < IN_CH; c++) s += relB[c] * c2_eww[c];
            g_ewc[1] = s + c2_ewb[0];
        }
    }
    gsync(0);

    // ---------------- P1: ew_hist (edges) + transform L1 (nodes) ----------------
    if (tid < REL_DIM) { sm.ew.sv1[tid] = g_v1[tid]; sm.ew.sv2[tid] = g_v2[tid]; }
    if (tid < 2) sm.ew.sc[tid] = g_ewc[tid];
    __syncthreads();
    {
        float c0 = sm.ew.sc[0], c1 = sm.ew.sc[1];
        for (int e = gtid; e < N_EDGES; e += GT) {
            const float4* rp = reinterpret_cast<const float4*>(r + (size_t)e * REL_DIM);
            float a1 = 0.f, a2 = 0.f;
#pragma unroll
            for (int q = 0; q < 8; q++) {
                float4 f = rp[q];
                a1 += f.x * sm.ew.sv1[4*q] + f.y * sm.ew.sv1[4*q+1] + f.z * sm.ew.sv1[4*q+2] + f.w * sm.ew.sv1[4*q+3];
                a2 += f.x * sm.ew.sv2[4*q] + f.y * sm.ew.sv2[4*q+1] + f.z * sm.ew.sv2[4*q+2] + f.w * sm.ew.sv2[4*q+3];
            }
            g_ew1[e] = a1 + c0;
            g_ew2[e] = a2 + c1;
            atomicAdd(&g_deg[dst[e]], 1);
        }
    }
    __syncthreads();
    do_transform(&sm, feat, c1_lw, c1_lb, c1_aiw, c1_aib, c1_ajw, c1_ajb, gwarp, lane);
    gsync(1);

    // ---------------- P2: scan1 (block-local) + alpha_max L1 ----------------
    if (blk < NCHUNK) {
        int i = blk * 256 + tid;
        int v = (i < N_NODES) ? g_deg[i] : 0;
        int x = v;
#pragma unroll
        for (int off = 1; off < 32; off <<= 1) {
            int y = __shfl_up_sync(0xffffffffu, x, off);
            if (lane >= off) x += y;
        }
        int wid = tid >> 5;
        if (lane == 31) sm.sc.wsum[wid] = x;
        __syncthreads();
        if (wid == 0) {
            int s = (lane < 8) ? sm.sc.wsum[lane] : 0;
#pragma unroll
            for (int off = 1; off < 8; off <<= 1) {
                int y = __shfl_up_sync(0xffffffffu, s, off);
                if (lane >= off) s += y;
            }
            if (lane < 8) sm.sc.wsum[lane] = s;
        }
        __syncthreads();
        int woff = (wid == 0) ? 0 : sm.sc.wsum[wid - 1];
        if (i < N_NODES) g_rowst[i] = woff + x - v;
        if (tid == 255) g_bsum[blk] = woff + x;
        __syncthreads();
    }
    do_alpha_max(src, dst, g_ew1, g_mkey1, gtid);
    gsync(2);

    // ---------------- P3: scan2 (block 0) + exp_sum L1 ----------------
    if (blk == 0) {
        int t = tid, wid = t >> 5;
        int v = (t < NCHUNK) ? g_bsum[t] : 0;
        int x = v;
#pragma unroll
        for (int off = 1; off < 32; off <<= 1) {
            int y = __shfl_up_sync(0xffffffffu, x, off);
            if (lane >= off) x += y;
        }
        if (lane == 31) sm.sc.wsum[wid] = x;
        __syncthreads();
        if (wid == 0) {
            int s = (lane < 8) ? sm.sc.wsum[lane] : 0;
#pragma unroll
            for (int off = 1; off < 8; off <<= 1) {
                int y = __shfl_up_sync(0xffffffffu, s, off);
                if (lane >= off) s += y;
            }
            if (lane < 8) sm.sc.wsum[lane] = s;
        }
        __syncthreads();
        int woff = (wid == 0) ? 0 : sm.sc.wsum[wid - 1];
        if (t < NCHUNK) g_boff[t] = woff + x - v;
        __syncthreads();
    }
    do_exp_sum(src, g_mkey1, g_ssum1, gtid);
    gsync(3);

    // ---------------- P4: scan3 ----------------
    for (int i = gtid; i < N_NODES; i += GT) {
        int v = g_rowst[i] + g_boff[i >> 8];
        g_rowst[i] = v;
        g_curs[i]  = v;
    }
    gsync(4);

    // ---------------- P5: scatter ----------------
    for (int i = gtid; i < N_EDGES; i += GT) {
        int p = atomicAdd(&g_curs[dst[i]], 1);
        g_edge[p] = make_int2(src[i], i);
    }
    gsync(5);

    // ---------------- P6: gather L1 -> g_h ----------------
    do_gather(&sm, r, relW, relB, g_ssum1, g_h, gwarp, lane);
    gsync(6);

    // ---------------- P7: transform L2 ----------------
    do_transform(&sm, g_h, c2_lw, c2_lb, c2_aiw, c2_aib, c2_ajw, c2_ajb, gwarp, lane);
    gsync(7);

    // ---------------- P8: alpha_max L2 ----------------
    do_alpha_max(src, dst, g_ew2, g_mkey2, gtid);
    gsync(8);

    // ---------------- P9: exp_sum L2 ----------------
    do_exp_sum(src, g_mkey2, g_ssum2, gtid);
    gsync(9);

    // ---------------- P10: gather L2 -> out ----------------
    do_gather(&sm, r, relW, relB, g_ssum2, out, gwarp, lane);
}

extern "C" void kernel_launch(void* const* d_in, const int* in_sizes, int n_in,
                              void* d_out, int out_size)
{
    const float* feat   = (const float*)d_in[0];
    const int*   eidx   = (const int*)  d_in[1];
    const float* r      = (const float*)d_in[2];
    const float* rel_w  = (const float*)d_in[3];
    const float* rel_b  = (const float*)d_in[4];
    const float* c1_lw  = (const float*)d_in[5];
    const float* c1_lb  = (const float*)d_in[6];
    const float* c1_aiw = (const float*)d_in[7];
    const float* c1_aib = (const float*)d_in[8];
    const float* c1_ajw = (const float*)d_in[9];
    const float* c1_ajb = (const float*)d_in[10];
    const float* c1_eww = (const float*)d_in[11];
    const float* c1_ewb = (const float*)d_in[12];
    const float* c2_lw  = (const float*)d_in[13];
    const float* c2_lb  = (const float*)d_in[14];
    const float* c2_aiw = (const float*)d_in[15];
    const float* c2_aib = (const float*)d_in[16];
    const float* c2_ajw = (const float*)d_in[17];
    const float* c2_ajb = (const float*)d_in[18];
    const float* c2_eww = (const float*)d_in[19];
    const float* c2_ewb = (const float*)d_in[20];
    float* out = (float*)d_out;

    const int* src = eidx;
    const int* dst = eidx + N_EDGES;

    k_main<<<NBLK, NTHR>>>(feat, src, dst, r, rel_w, rel_b,
                           c1_lw, c1_lb, c1_aiw, c1_aib, c1_ajw, c1_ajb, c1_eww, c1_ewb,
                           c2_lw, c2_lb, c2_aiw, c2_aib, c2_ajw, c2_ajb, c2_eww, c2_ewb,
                           out);
}